// round 8
// baseline (speedup 1.0000x reference)
#include <cuda_runtime.h>
#include <cuda_bf16.h>
#include <cstdint>

// Tree: DIM=3, FBITS=8, K=4, DEPTH=10. POS[t]=(4^t-1)/3.
// Identity (verified R4, rel_err 3e-8): with full 30-bit reversal,
//   X_rev = sum_t rev3(j_t) << 3t; c0=X&1023, c1=(X>>10)&1023, c2=X>>20.
//
// Decomposition: 1 thread = level-9 node n9 (4 leaves, 12 floats out).
// Block of 256 covers n9 in [256*b, 256*b+256):
//   levels 0..4: node+rank block-uniform  -> thread 0 -> s_pre (15 bits)
//   level  5   : node uniform, rank = (n9>>6)&3 -> thread 0 loads pack -> s_p5
//   levels 6..8: per-thread LDG (L1-broadcast within block) + shared-LUT
//   level  9   : per-thread LDG (coalesced), pack covers all 4 leaves

#define BLOCK   256
#define NBLOCKS 1024     // 262144 level-9 nodes

__device__ __forceinline__ unsigned packbyte(unsigned v)
{
    // packed rev3(bit position) of set bits of byte v, 3 bits per rank
    unsigned packed = 0;
    int rank = 0;
    #pragma unroll
    for (int b = 0; b < 8; ++b) {
        if ((v >> b) & 1u) {
            unsigned rb = ((b & 1u) << 2) | (b & 2u) | ((b >> 2) & 1u); // rev3
            if (rank < 8) packed |= rb << (3 * rank);
            ++rank;
        }
    }
    return packed;
}

__global__ void __launch_bounds__(BLOCK)
nbit_decode_kernel(const int* __restrict__ flags,
                   const float* __restrict__ offset,
                   const float* __restrict__ scale,
                   float* __restrict__ out)
{
    __shared__ unsigned lut[256];
    __shared__ unsigned s_pre;   // levels 0..4 accumulated (bits 0..14)
    __shared__ unsigned s_p5;    // lut-pack of the level-5 flag

    const int tid = threadIdx.x;
    const unsigned n9base = blockIdx.x * BLOCK;

    // Every thread builds one LUT entry; thread 0 additionally computes the
    // block-uniform prefix arithmetically (no lut dependency -> single sync).
    lut[tid] = packbyte((unsigned)tid);

    if (tid == 0) {
        const int P[5] = {0, 1, 5, 21, 85};
        unsigned acc = 0;
        #pragma unroll
        for (int t = 0; t < 5; ++t) {
            unsigned nt = n9base >> (2 * (9 - t));
            unsigned rt = (n9base >> (2 * (8 - t))) & 3u;
            unsigned f  = ((unsigned)flags[P[t] + (int)nt]) & 255u;
            acc |= ((packbyte(f) >> (3 * rt)) & 7u) << (3 * t);
        }
        s_pre = acc;
        // level-5 node for this block = n9base >> 8 = blockIdx.x
        s_p5 = packbyte(((unsigned)flags[341 + blockIdx.x]) & 255u);
    }
    __syncthreads();

    const unsigned n9 = n9base + (unsigned)tid;

    // Issue all 4 global loads up front (MLP=4)
    const unsigned f6 = ((unsigned)__ldg(&flags[1365  + (int)(n9 >> 6)])) & 255u;
    const unsigned f7 = ((unsigned)__ldg(&flags[5461  + (int)(n9 >> 4)])) & 255u;
    const unsigned f8 = ((unsigned)__ldg(&flags[21845 + (int)(n9 >> 2)])) & 255u;
    const unsigned f9 = ((unsigned)__ldg(&flags[87381 + (int)n9]))        & 255u;

    unsigned acc = s_pre;
    acc |= ((s_p5    >> (3u * ((n9 >> 6) & 3u))) & 7u) << 15;  // level 5
    acc |= ((lut[f6] >> (3u * ((n9 >> 4) & 3u))) & 7u) << 18;  // level 6
    acc |= ((lut[f7] >> (3u * ((n9 >> 2) & 3u))) & 7u) << 21;  // level 7
    acc |= ((lut[f8] >> (3u * ( n9        & 3u))) & 7u) << 24; // level 8
    const unsigned p9 = lut[f9];                               // level 9 pack

    const float s0 = __ldg(&scale[0]),  s1 = __ldg(&scale[1]),  s2 = __ldg(&scale[2]);
    const float o0 = __ldg(&offset[0]), o1 = __ldg(&offset[1]), o2 = __ldg(&offset[2]);

    // c0, c1 shared by the 4 leaves; c2 varies only in its top 3 bits
    const float v0    = (float)(acc & 1023u)         * s0 + o0;
    const float v1    = (float)((acc >> 10) & 1023u) * s1 + o1;
    const float fbase = (float)((acc >> 20) & 127u)  * s2 + o2;
    const float s2h   = s2 * 128.0f;

    const float vc0 = (float)( p9        & 7u) * s2h + fbase;
    const float vc1 = (float)((p9 >> 3)  & 7u) * s2h + fbase;
    const float vc2 = (float)((p9 >> 6)  & 7u) * s2h + fbase;
    const float vc3 = (float)((p9 >> 9)  & 7u) * s2h + fbase;

    float4* o4 = reinterpret_cast<float4*>(out + (size_t)n9 * 12u);
    o4[0] = make_float4(v0,  v1,  vc0, v0);
    o4[1] = make_float4(v1,  vc1, v0,  v1);
    o4[2] = make_float4(vc2, v0,  v1,  vc3);
}

extern "C" void kernel_launch(void* const* d_in, const int* in_sizes, int n_in,
                              void* d_out, int out_size)
{
    const int*   flags  = (const int*)  d_in[0];
    const float* offset = (const float*)d_in[1];
    const float* scale  = (const float*)d_in[2];
    if (n_in == 3 && in_sizes[0] == 3) {   // defensive input-order handling
        int fi = (in_sizes[1] > 3) ? 1 : 2;
        flags = (const int*)d_in[fi];
        int s1 = -1, s2 = -1;
        for (int i = 0; i < 3; ++i) {
            if (i == fi) continue;
            if (s1 < 0) s1 = i; else s2 = i;
        }
        offset = (const float*)d_in[s1];
        scale  = (const float*)d_in[s2];
    }

    nbit_decode_kernel<<<NBLOCKS, BLOCK>>>(flags, offset, scale, (float*)d_out);
}

// round 10
// speedup vs baseline: 1.3506x; 1.3506x over previous
#include <cuda_runtime.h>
#include <cuda_bf16.h>
#include <cstdint>

// Tree: DIM=3, FBITS=8, K=4, DEPTH=10. POS[t]=(4^t-1)/3.
// Identity (verified since R4, rel_err ~3e-8): with full 30-bit reversal,
//   X_rev = sum_t rev3(j_t) << 3t; c0=X&1023, c1=(X>>10)&1023, c2=X>>20.
//
// R9: 1 thread = level-9 node (4 leaves, 12 floats). Grid 2048x128 so
// occupancy is no longer grid-limited (R4/R6 were stuck at ~57%).
// LUT is compile-time; threads copy it to shared (no packbyte at runtime,
// no serial thread-0 section). All 10 flag loads issued up front (MLP=10);
// levels 0..5 are block-uniform addresses -> L1-broadcast wavefronts.

#define BLOCK   128
#define NBLOCKS 2048     // 262144 level-9 nodes

constexpr unsigned packbyte_c(unsigned v)
{
    unsigned packed = 0;
    int rank = 0;
    for (int b = 0; b < 8; ++b)
        if ((v >> b) & 1u) {
            unsigned rb = ((b & 1u) << 2) | (b & 2u) | ((b >> 2) & 1u); // rev3
            if (rank < 8) packed |= rb << (3 * rank);
            ++rank;
        }
    return packed;
}

#define L1E(n)  packbyte_c(n)
#define L4E(n)  L1E(n), L1E((n)+1), L1E((n)+2), L1E((n)+3)
#define L16E(n) L4E(n), L4E((n)+4), L4E((n)+8), L4E((n)+12)
#define L64E(n) L16E(n), L16E((n)+16), L16E((n)+32), L16E((n)+48)
__device__ const unsigned g_lut[256] = { L64E(0), L64E(64), L64E(128), L64E(192) };

__global__ void __launch_bounds__(BLOCK, 16)
nbit_decode_kernel(const int* __restrict__ flags,
                   const float* __restrict__ offset,
                   const float* __restrict__ scale,
                   float* __restrict__ out)
{
    __shared__ unsigned lut[256];
    const int tid = threadIdx.x;

    // Cooperative LUT copy: 128 threads x uint2 = 1KB, fully coalesced.
    reinterpret_cast<uint2*>(lut)[tid] =
        reinterpret_cast<const uint2*>(g_lut)[tid];
    __syncthreads();

    const unsigned n9 = blockIdx.x * BLOCK + (unsigned)tid;

    // Issue all flag loads up front. Levels 0..5 are block-uniform.
    const unsigned fl0 = (unsigned)__ldg(&flags[0])                       & 255u;
    const unsigned fl1 = (unsigned)__ldg(&flags[1     + (int)(n9 >> 16)]) & 255u;
    const unsigned fl2 = (unsigned)__ldg(&flags[5     + (int)(n9 >> 14)]) & 255u;
    const unsigned fl3 = (unsigned)__ldg(&flags[21    + (int)(n9 >> 12)]) & 255u;
    const unsigned fl4 = (unsigned)__ldg(&flags[85    + (int)(n9 >> 10)]) & 255u;
    const unsigned fl5 = (unsigned)__ldg(&flags[341   + (int)(n9 >> 8)])  & 255u;
    const unsigned fl6 = (unsigned)__ldg(&flags[1365  + (int)(n9 >> 6)])  & 255u;
    const unsigned fl7 = (unsigned)__ldg(&flags[5461  + (int)(n9 >> 4)])  & 255u;
    const unsigned fl8 = (unsigned)__ldg(&flags[21845 + (int)(n9 >> 2)])  & 255u;
    const unsigned fl9 = (unsigned)__ldg(&flags[87381 + (int)n9])         & 255u;

    unsigned acc;
    acc  = ((lut[fl0] >> (3u * ((n9 >> 16) & 3u))) & 7u);
    acc |= ((lut[fl1] >> (3u * ((n9 >> 14) & 3u))) & 7u) << 3;
    acc |= ((lut[fl2] >> (3u * ((n9 >> 12) & 3u))) & 7u) << 6;
    acc |= ((lut[fl3] >> (3u * ((n9 >> 10) & 3u))) & 7u) << 9;
    acc |= ((lut[fl4] >> (3u * ((n9 >>  8) & 3u))) & 7u) << 12;
    acc |= ((lut[fl5] >> (3u * ((n9 >>  6) & 3u))) & 7u) << 15;
    acc |= ((lut[fl6] >> (3u * ((n9 >>  4) & 3u))) & 7u) << 18;
    acc |= ((lut[fl7] >> (3u * ((n9 >>  2) & 3u))) & 7u) << 21;
    acc |= ((lut[fl8] >> (3u * ( n9        & 3u))) & 7u) << 24;
    const unsigned p9 = lut[fl9];   // level 9: all 4 leaf contributions

    const float s0 = __ldg(&scale[0]),  s1 = __ldg(&scale[1]),  s2 = __ldg(&scale[2]);
    const float o0 = __ldg(&offset[0]), o1 = __ldg(&offset[1]), o2 = __ldg(&offset[2]);

    // c0, c1 shared by this thread's 4 leaves; c2 varies only in its top 3 bits.
    const float v0    = (float)(acc & 1023u)         * s0 + o0;
    const float v1    = (float)((acc >> 10) & 1023u) * s1 + o1;
    const float fbase = (float)((acc >> 20) & 127u)  * s2 + o2;
    const float s2h   = s2 * 128.0f;

    const float vc0 = (float)( p9        & 7u) * s2h + fbase;
    const float vc1 = (float)((p9 >> 3)  & 7u) * s2h + fbase;
    const float vc2 = (float)((p9 >> 6)  & 7u) * s2h + fbase;
    const float vc3 = (float)((p9 >> 9)  & 7u) * s2h + fbase;

    float4* o4 = reinterpret_cast<float4*>(out + (size_t)n9 * 12u);
    o4[0] = make_float4(v0,  v1,  vc0, v0);
    o4[1] = make_float4(v1,  vc1, v0,  v1);
    o4[2] = make_float4(vc2, v0,  v1,  vc3);
}

extern "C" void kernel_launch(void* const* d_in, const int* in_sizes, int n_in,
                              void* d_out, int out_size)
{
    const int*   flags  = (const int*)  d_in[0];
    const float* offset = (const float*)d_in[1];
    const float* scale  = (const float*)d_in[2];
    if (n_in == 3 && in_sizes[0] == 3) {   // defensive input-order handling
        int fi = (in_sizes[1] > 3) ? 1 : 2;
        flags = (const int*)d_in[fi];
        int s1 = -1, s2 = -1;
        for (int i = 0; i < 3; ++i) {
            if (i == fi) continue;
            if (s1 < 0) s1 = i; else s2 = i;
        }
        offset = (const float*)d_in[s1];
        scale  = (const float*)d_in[s2];
    }

    nbit_decode_kernel<<<NBLOCKS, BLOCK>>>(flags, offset, scale, (float*)d_out);
}